// round 3
// baseline (speedup 1.0000x reference)
#include <cuda_runtime.h>
#include <cuda_bf16.h>
#include <cstdint>

#define NCONCEPTS 4096
#define CDIM      1024
#define BATCH     4096
#define KSAMP     256

// Scratch for per-concept dot products (no cudaMalloc allowed).
__device__ float g_s[NCONCEPTS];

// One warp per concept row: s[c] = sum_d cb[c,d] * A[c,d]
// 8 warps (256 threads) per block -> 512 blocks.
__global__ void __launch_bounds__(256) dot_rows_kernel(
    const float* __restrict__ cb,
    const float* __restrict__ at)
{
    const int row  = blockIdx.x * 8 + (threadIdx.x >> 5);
    const int lane = threadIdx.x & 31;

    const float4* __restrict__ a = reinterpret_cast<const float4*>(cb + (size_t)row * CDIM);
    const float4* __restrict__ b = reinterpret_cast<const float4*>(at + (size_t)row * CDIM);

    float acc = 0.0f;
#pragma unroll
    for (int i = 0; i < CDIM / 4 / 32; ++i) {   // 8 iterations
        float4 x = a[lane + i * 32];
        float4 y = b[lane + i * 32];
        acc += x.x * y.x + x.y * y.y + x.z * y.z + x.w * y.w;
    }
#pragma unroll
    for (int off = 16; off > 0; off >>= 1)
        acc += __shfl_xor_sync(0xffffffffu, acc, off);

    if (lane == 0)
        g_s[row] = acc;
}

// Fused zero + scatter: one block per batch row b.
// Phase 1: 256 threads zero the 4096-float row with float4 stores.
// Phase 2: thread t writes out[b, idx[b,t]] = g_s[idx[b,t]].
// sampled_idx is int32 on-device (JAX default x32 downcasts the declared int64).
// Duplicate indices write the same value -> benign.
__global__ void __launch_bounds__(256) zero_scatter_kernel(
    const int* __restrict__ idx,
    float* __restrict__ out)
{
    const int b = blockIdx.x;
    const int t = threadIdx.x;

    float4* __restrict__ row4 = reinterpret_cast<float4*>(out + (size_t)b * NCONCEPTS);
    const float4 z = make_float4(0.f, 0.f, 0.f, 0.f);
#pragma unroll
    for (int i = 0; i < NCONCEPTS / 4 / 256; ++i)   // 4 iterations
        row4[t + i * 256] = z;

    __syncthreads();

    const int c = idx[b * KSAMP + t];
    out[(size_t)b * NCONCEPTS + c] = g_s[c];
}

extern "C" void kernel_launch(void* const* d_in, const int* in_sizes, int n_in,
                              void* d_out, int out_size)
{
    const float* cb  = (const float*)d_in[0];
    const float* at  = (const float*)d_in[1];
    const int*   idx = (const int*)d_in[2];
    float*       out = (float*)d_out;

    // 1) per-concept dots
    dot_rows_kernel<<<NCONCEPTS / 8, 256>>>(cb, at);

    // 2) fused zero + scatter
    zero_scatter_kernel<<<BATCH, 256>>>(idx, out);
}